// round 2
// baseline (speedup 1.0000x reference)
#include <cuda_runtime.h>
#include <math.h>

// Problem constants
#define BB 2
#define NN 2048
#define CC 1024
#define HH 16
#define HD 64
#define HID 4096
#define MTOK (BB * NN)          // 4096 tokens
#define SCALE 0.125f            // HD^-0.5

// ---------------------------------------------------------------------------
// Scratch (device globals; no allocation allowed)
// ---------------------------------------------------------------------------
__device__ float g_qkv [MTOK * 3 * CC];   // 50 MB
__device__ float g_ctx [MTOK * CC];       // 16 MB
__device__ float g_proj[MTOK * CC];       // 16 MB
__device__ float g_y1  [MTOK * CC];       // 16 MB
__device__ float g_h   [MTOK * HID];      // 64 MB
__device__ float g_mlp [MTOK * CC];       // 16 MB

// ---------------------------------------------------------------------------
// Helpers
// ---------------------------------------------------------------------------
__device__ __forceinline__ float gelu_exact(float v) {
    return 0.5f * v * (1.0f + erff(v * 0.70710678118654752440f));
}

// ---------------------------------------------------------------------------
// GEMM: Y[M,N] = X[M,K] @ W[N,K]^T (+bias) (+gelu)
// Both operands row-major with K contiguous (NT layout).
// BM=BN=128, BK=16, 256 threads, 8x8 register tile per thread.
// Double-buffered shared memory with register prefetch.
// All dims are multiples of tile sizes for this problem -> no bounds checks.
// ---------------------------------------------------------------------------
__global__ void __launch_bounds__(256)
gemm_nt_kernel(const float* __restrict__ X, const float* __restrict__ W,
               const float* __restrict__ bias, float* __restrict__ Y,
               int M, int N, int K, int act)
{
    __shared__ float As[2][16][128];
    __shared__ float Bs[2][16][128];

    const int tid = threadIdx.x;
    const int m0 = blockIdx.y * 128;
    const int n0 = blockIdx.x * 128;

    // global->shared load mapping: each thread loads 8 contiguous floats
    // (2 float4) of one row of A and one row of B per K-tile.
    const int lr = tid >> 1;            // 0..127 (row within tile)
    const int lc = (tid & 1) << 3;      // 0 or 8 (k offset)
    const float* Ap = X + (size_t)(m0 + lr) * K + lc;
    const float* Bp = W + (size_t)(n0 + lr) * K + lc;

    // compute mapping: 16x16 thread grid, each thread 8x8 outputs
    const int tr = tid >> 4;            // 0..15
    const int tc = tid & 15;            // 0..15

    float acc[8][8];
#pragma unroll
    for (int i = 0; i < 8; i++)
#pragma unroll
        for (int j = 0; j < 8; j++) acc[i][j] = 0.0f;

    // preload tile 0 into buffer 0
    {
        float4 a0 = *(const float4*)(Ap + 0);
        float4 a1 = *(const float4*)(Ap + 4);
        float4 b0 = *(const float4*)(Bp + 0);
        float4 b1 = *(const float4*)(Bp + 4);
        As[0][lc + 0][lr] = a0.x; As[0][lc + 1][lr] = a0.y;
        As[0][lc + 2][lr] = a0.z; As[0][lc + 3][lr] = a0.w;
        As[0][lc + 4][lr] = a1.x; As[0][lc + 5][lr] = a1.y;
        As[0][lc + 6][lr] = a1.z; As[0][lc + 7][lr] = a1.w;
        Bs[0][lc + 0][lr] = b0.x; Bs[0][lc + 1][lr] = b0.y;
        Bs[0][lc + 2][lr] = b0.z; Bs[0][lc + 3][lr] = b0.w;
        Bs[0][lc + 4][lr] = b1.x; Bs[0][lc + 5][lr] = b1.y;
        Bs[0][lc + 6][lr] = b1.z; Bs[0][lc + 7][lr] = b1.w;
    }
    __syncthreads();

    const int T = K >> 4;               // number of K-tiles
    int buf = 0;
    for (int t = 0; t < T; t++) {
        float4 a0n, a1n, b0n, b1n;
        const bool more = (t + 1 < T);
        if (more) {
            const int k0 = (t + 1) << 4;
            a0n = *(const float4*)(Ap + k0);
            a1n = *(const float4*)(Ap + k0 + 4);
            b0n = *(const float4*)(Bp + k0);
            b1n = *(const float4*)(Bp + k0 + 4);
        }

#pragma unroll
        for (int kk = 0; kk < 16; kk++) {
            float4 af0 = *(const float4*)&As[buf][kk][tr * 8];
            float4 af1 = *(const float4*)&As[buf][kk][tr * 8 + 4];
            float4 bf0 = *(const float4*)&Bs[buf][kk][tc * 8];
            float4 bf1 = *(const float4*)&Bs[buf][kk][tc * 8 + 4];
            float a[8] = {af0.x, af0.y, af0.z, af0.w, af1.x, af1.y, af1.z, af1.w};
            float b[8] = {bf0.x, bf0.y, bf0.z, bf0.w, bf1.x, bf1.y, bf1.z, bf1.w};
#pragma unroll
            for (int i = 0; i < 8; i++)
#pragma unroll
                for (int j = 0; j < 8; j++)
                    acc[i][j] = fmaf(a[i], b[j], acc[i][j]);
        }

        if (more) {
            const int nb = buf ^ 1;
            As[nb][lc + 0][lr] = a0n.x; As[nb][lc + 1][lr] = a0n.y;
            As[nb][lc + 2][lr] = a0n.z; As[nb][lc + 3][lr] = a0n.w;
            As[nb][lc + 4][lr] = a1n.x; As[nb][lc + 5][lr] = a1n.y;
            As[nb][lc + 6][lr] = a1n.z; As[nb][lc + 7][lr] = a1n.w;
            Bs[nb][lc + 0][lr] = b0n.x; Bs[nb][lc + 1][lr] = b0n.y;
            Bs[nb][lc + 2][lr] = b0n.z; Bs[nb][lc + 3][lr] = b0n.w;
            Bs[nb][lc + 4][lr] = b1n.x; Bs[nb][lc + 5][lr] = b1n.y;
            Bs[nb][lc + 6][lr] = b1n.z; Bs[nb][lc + 7][lr] = b1n.w;
            __syncthreads();
            buf = nb;
        }
    }

    // epilogue
    float bv[8];
#pragma unroll
    for (int j = 0; j < 8; j++)
        bv[j] = bias ? bias[n0 + tc * 8 + j] : 0.0f;

#pragma unroll
    for (int i = 0; i < 8; i++) {
        const int m = m0 + tr * 8 + i;
        float* yp = Y + (size_t)m * N + n0 + tc * 8;
        float out[8];
#pragma unroll
        for (int j = 0; j < 8; j++) {
            float v = acc[i][j] + bv[j];
            if (act) v = gelu_exact(v);
            out[j] = v;
        }
        *(float4*)(yp + 0) = make_float4(out[0], out[1], out[2], out[3]);
        *(float4*)(yp + 4) = make_float4(out[4], out[5], out[6], out[7]);
    }
}

// ---------------------------------------------------------------------------
// Flash attention (fp32, online softmax).
// grid: (N/64, B*H); block: 128 threads. BQ=64, BK=32, HD=64.
// Thread t handles q-row t/2; (t&1) selects a 32-dim half for P@V
// and a 16-column half of the 32 keys for S.
// Static shared memory (<= 48 KB) -> no cudaFuncSetAttribute needed.
// ---------------------------------------------------------------------------
#define APAD 68
#define PPAD 36

__global__ void __launch_bounds__(128)
attn_kernel(const float* __restrict__ qkv, float* __restrict__ ctx)
{
    __shared__ float Qs[64][APAD];      // 17408 B
    __shared__ float Ks[32][APAD];      //  8704 B
    __shared__ float Vs[32][APAD];      //  8704 B
    __shared__ float Ps[64][PPAD];      //  9216 B   -> total 44032 B

    const int bh = blockIdx.y;
    const int b = bh >> 4;
    const int h = bh & 15;
    const int q0 = blockIdx.x * 64;
    const int tid = threadIdx.x;
    const int row  = tid >> 1;        // 0..63
    const int half = tid & 1;
    const int doff = half * 32;       // this thread's dim half (P@V)
    const int joff = half * 16;       // this thread's key-column half (S)

    // load Q tile (scaled)
    for (int idx = tid; idx < 64 * 16; idx += 128) {
        const int i = idx >> 4;
        const int d4 = (idx & 15) << 2;
        const float* p = qkv + (size_t)(b * NN + q0 + i) * (3 * CC) + h * HD + d4;
        float4 v = *(const float4*)p;
        Qs[i][d4 + 0] = v.x * SCALE; Qs[i][d4 + 1] = v.y * SCALE;
        Qs[i][d4 + 2] = v.z * SCALE; Qs[i][d4 + 3] = v.w * SCALE;
    }

    float m = -INFINITY, l = 0.0f;
    float acc[32];
#pragma unroll
    for (int d = 0; d < 32; d++) acc[d] = 0.0f;

    for (int k0 = 0; k0 < NN; k0 += 32) {
        // load K,V tiles (32 rows x 64 dims each)
        for (int idx = tid; idx < 32 * 16; idx += 128) {
            const int j = idx >> 4;
            const int d4 = (idx & 15) << 2;
            const size_t base = (size_t)(b * NN + k0 + j) * (3 * CC) + h * HD + d4;
            float4 kv = *(const float4*)(qkv + CC + base);
            float4 vv = *(const float4*)(qkv + 2 * CC + base);
            Ks[j][d4 + 0] = kv.x; Ks[j][d4 + 1] = kv.y;
            Ks[j][d4 + 2] = kv.z; Ks[j][d4 + 3] = kv.w;
            Vs[j][d4 + 0] = vv.x; Vs[j][d4 + 1] = vv.y;
            Vs[j][d4 + 2] = vv.z; Vs[j][d4 + 3] = vv.w;
        }
        __syncthreads();

        // S = Q @ K^T  (this thread: row `row`, cols joff..joff+15)
        float s[16];
#pragma unroll
        for (int jj = 0; jj < 16; jj++) s[jj] = 0.0f;

#pragma unroll
        for (int d0 = 0; d0 < 64; d0 += 16) {
            float4 qa = *(const float4*)&Qs[row][d0 + 0];
            float4 qb = *(const float4*)&Qs[row][d0 + 4];
            float4 qc = *(const float4*)&Qs[row][d0 + 8];
            float4 qd = *(const float4*)&Qs[row][d0 + 12];
#pragma unroll 4
            for (int jj = 0; jj < 16; jj++) {
                const float* kr = &Ks[joff + jj][d0];
                float4 ka = *(const float4*)(kr + 0);
                float4 kb = *(const float4*)(kr + 4);
                float4 kc = *(const float4*)(kr + 8);
                float4 kd = *(const float4*)(kr + 12);
                float t = s[jj];
                t = fmaf(qa.x, ka.x, t); t = fmaf(qa.y, ka.y, t);
                t = fmaf(qa.z, ka.z, t); t = fmaf(qa.w, ka.w, t);
                t = fmaf(qb.x, kb.x, t); t = fmaf(qb.y, kb.y, t);
                t = fmaf(qb.z, kb.z, t); t = fmaf(qb.w, kb.w, t);
                t = fmaf(qc.x, kc.x, t); t = fmaf(qc.y, kc.y, t);
                t = fmaf(qc.z, kc.z, t); t = fmaf(qc.w, kc.w, t);
                t = fmaf(qd.x, kd.x, t); t = fmaf(qd.y, kd.y, t);
                t = fmaf(qd.z, kd.z, t); t = fmaf(qd.w, kd.w, t);
                s[jj] = t;
            }
        }

        // online softmax update (pair = lanes (2r, 2r+1), same warp)
        float tmax = -INFINITY;
#pragma unroll
        for (int jj = 0; jj < 16; jj++) tmax = fmaxf(tmax, s[jj]);
        tmax = fmaxf(tmax, __shfl_xor_sync(0xffffffffu, tmax, 1));
        const float mnew = fmaxf(m, tmax);
        const float alpha = __expf(m - mnew);
        float lsum = 0.0f;
#pragma unroll
        for (int jj = 0; jj < 16; jj++) {
            float p = __expf(s[jj] - mnew);
            Ps[row][joff + jj] = p;
            lsum += p;
        }
        lsum += __shfl_xor_sync(0xffffffffu, lsum, 1);
        l = l * alpha + lsum;
        m = mnew;
#pragma unroll
        for (int d = 0; d < 32; d++) acc[d] *= alpha;
        __syncwarp();   // partner's Ps half visible (same warp)

        // acc += P @ V  (this thread: all 32 j, dims doff..doff+31)
#pragma unroll 4
        for (int j = 0; j < 32; j++) {
            const float p = Ps[row][j];
            const float* vr = &Vs[j][doff];
#pragma unroll
            for (int d4 = 0; d4 < 32; d4 += 4) {
                float4 v = *(const float4*)(vr + d4);
                acc[d4 + 0] = fmaf(p, v.x, acc[d4 + 0]);
                acc[d4 + 1] = fmaf(p, v.y, acc[d4 + 1]);
                acc[d4 + 2] = fmaf(p, v.z, acc[d4 + 2]);
                acc[d4 + 3] = fmaf(p, v.w, acc[d4 + 3]);
            }
        }
        __syncthreads();  // before K/V overwrite next iteration
    }

    const float inv = 1.0f / l;
    float* out = ctx + (size_t)(b * NN + q0 + row) * CC + h * HD + doff;
#pragma unroll
    for (int d4 = 0; d4 < 32; d4 += 4) {
        *(float4*)(out + d4) = make_float4(acc[d4] * inv, acc[d4 + 1] * inv,
                                           acc[d4 + 2] * inv, acc[d4 + 3] * inv);
    }
}

// ---------------------------------------------------------------------------
// dst[row] = base[row] + LayerNorm(x[row]) * w + b    (row length = 1024)
// one block (256 threads) per row; float4 per thread.
// ---------------------------------------------------------------------------
__global__ void __launch_bounds__(256)
residual_ln_kernel(const float* __restrict__ base, const float* __restrict__ x,
                   const float* __restrict__ w, const float* __restrict__ bvec,
                   float* __restrict__ dst)
{
    __shared__ float s_sum[8], s_sq[8];
    const int rowid = blockIdx.x;
    const int tid = threadIdx.x;
    const float4* xr = (const float4*)(x + (size_t)rowid * CC);

    float4 v = xr[tid];
    float sum = v.x + v.y + v.z + v.w;
    float sq  = v.x * v.x + v.y * v.y + v.z * v.z + v.w * v.w;

    const int lane = tid & 31, wid = tid >> 5;
#pragma unroll
    for (int o = 16; o; o >>= 1) {
        sum += __shfl_xor_sync(0xffffffffu, sum, o);
        sq  += __shfl_xor_sync(0xffffffffu, sq,  o);
    }
    if (lane == 0) { s_sum[wid] = sum; s_sq[wid] = sq; }
    __syncthreads();
    if (wid == 0) {
        sum = (lane < 8) ? s_sum[lane] : 0.0f;
        sq  = (lane < 8) ? s_sq[lane]  : 0.0f;
#pragma unroll
        for (int o = 4; o; o >>= 1) {
            sum += __shfl_xor_sync(0xffffffffu, sum, o);
            sq  += __shfl_xor_sync(0xffffffffu, sq,  o);
        }
        if (lane == 0) { s_sum[0] = sum; s_sq[0] = sq; }
    }
    __syncthreads();

    const float mu = s_sum[0] * (1.0f / CC);
    const float var = s_sq[0] * (1.0f / CC) - mu * mu;
    const float rstd = rsqrtf(var + 1e-5f);

    const float4* br = (const float4*)(base + (size_t)rowid * CC);
    const float4* wr = (const float4*)w;
    const float4* bb = (const float4*)bvec;
    float4 bs = br[tid], wv = wr[tid], bvv = bb[tid];
    float4 o;
    o.x = bs.x + (v.x - mu) * rstd * wv.x + bvv.x;
    o.y = bs.y + (v.y - mu) * rstd * wv.y + bvv.y;
    o.z = bs.z + (v.z - mu) * rstd * wv.z + bvv.z;
    o.w = bs.w + (v.w - mu) * rstd * wv.w + bvv.w;
    ((float4*)(dst + (size_t)rowid * CC))[tid] = o;
}

// ---------------------------------------------------------------------------
// Launch
// ---------------------------------------------------------------------------
extern "C" void kernel_launch(void* const* d_in, const int* in_sizes, int n_in,
                              void* d_out, int out_size)
{
    const float* x      = (const float*)d_in[0];
    const float* qkv_w  = (const float*)d_in[1];
    const float* proj_w = (const float*)d_in[2];
    const float* proj_b = (const float*)d_in[3];
    const float* ln1_w  = (const float*)d_in[4];
    const float* ln1_b  = (const float*)d_in[5];
    const float* fc1_w  = (const float*)d_in[6];
    const float* fc1_b  = (const float*)d_in[7];
    const float* fc2_w  = (const float*)d_in[8];
    const float* fc2_b  = (const float*)d_in[9];
    const float* ln2_w  = (const float*)d_in[10];
    const float* ln2_b  = (const float*)d_in[11];
    float* out = (float*)d_out;

    float *qkv, *ctx, *proj, *y1, *hbuf, *mlp;
    cudaGetSymbolAddress((void**)&qkv,  g_qkv);
    cudaGetSymbolAddress((void**)&ctx,  g_ctx);
    cudaGetSymbolAddress((void**)&proj, g_proj);
    cudaGetSymbolAddress((void**)&y1,   g_y1);
    cudaGetSymbolAddress((void**)&hbuf, g_h);
    cudaGetSymbolAddress((void**)&mlp,  g_mlp);

    // 1. qkv = x @ qkv_w^T                       [4096, 3072]
    gemm_nt_kernel<<<dim3(3 * CC / 128, MTOK / 128), 256>>>(
        x, qkv_w, nullptr, qkv, MTOK, 3 * CC, CC, 0);

    // 2. attention -> ctx                        [4096, 1024]
    attn_kernel<<<dim3(NN / 64, BB * HH), 128>>>(qkv, ctx);

    // 3. proj = ctx @ proj_w^T + proj_b          [4096, 1024]
    gemm_nt_kernel<<<dim3(CC / 128, MTOK / 128), 256>>>(
        ctx, proj_w, proj_b, proj, MTOK, CC, CC, 0);

    // 4. y1 = proj + LN(proj)
    residual_ln_kernel<<<MTOK, 256>>>(proj, proj, ln1_w, ln1_b, y1);

    // 5. h = gelu(y1 @ fc1_w^T + fc1_b)          [4096, 4096]
    gemm_nt_kernel<<<dim3(HID / 128, MTOK / 128), 256>>>(
        y1, fc1_w, fc1_b, hbuf, MTOK, HID, CC, 1);

    // 6. mlp = h @ fc2_w^T + fc2_b               [4096, 1024]
    gemm_nt_kernel<<<dim3(CC / 128, MTOK / 128), 256>>>(
        hbuf, fc2_w, fc2_b, mlp, MTOK, CC, HID, 0);

    // 7. out = y1 + LN(mlp)
    residual_ln_kernel<<<MTOK, 256>>>(y1, mlp, ln2_w, ln2_b, out);
}

// round 3
// speedup vs baseline: 1.4184x; 1.4184x over previous
#include <cuda_runtime.h>
#include <math.h>

// Problem constants
#define BB 2
#define NN 2048
#define CC 1024
#define HH 16
#define HD 64
#define HID 4096
#define MTOK (BB * NN)          // 4096 tokens
#define SCALE 0.125f            // HD^-0.5

// ---------------------------------------------------------------------------
// Scratch (device globals; no allocation allowed)
// ---------------------------------------------------------------------------
__device__ float g_qkv [MTOK * 3 * CC];   // 50 MB
__device__ float g_ctx [MTOK * CC];       // 16 MB
__device__ float g_proj[MTOK * CC];       // 16 MB
__device__ float g_y1  [MTOK * CC];       // 16 MB
__device__ float g_h   [MTOK * HID];      // 64 MB
__device__ float g_mlp [MTOK * CC];       // 16 MB

// ---------------------------------------------------------------------------
// Helpers
// ---------------------------------------------------------------------------
__device__ __forceinline__ float gelu_exact(float v) {
    return 0.5f * v * (1.0f + erff(v * 0.70710678118654752440f));
}

__device__ __forceinline__ float to_tf32(float x) {
    unsigned u;
    asm("cvt.rna.tf32.f32 %0, %1;" : "=r"(u) : "f"(x));
    return __uint_as_float(u);
}

// ---------------------------------------------------------------------------
// Tensor-core GEMM (tf32 mma.sync): Y[M,N] = X[M,K] @ W[N,K]^T (+bias)(+gelu)
// Both operands row-major, K contiguous (NT layout).
// BM=BN=128, BK=16, 256 threads = 8 warps in 2(m) x 4(n) grid.
// Warp tile 64x32 = 4x4 mma tiles of m16n8k8.
// Smem k-major [16][136]: pad 8 floats -> 136 mod 32 = 8 banks between k-rows,
// so the 4 quad-groups of a fragment load hit disjoint bank octets (no conflicts).
// ---------------------------------------------------------------------------
#define GPAD 136

__global__ void __launch_bounds__(256, 2)
gemm_tc_kernel(const float* __restrict__ X, const float* __restrict__ W,
               const float* __restrict__ bias, float* __restrict__ Y,
               int M, int N, int K, int act)
{
    __shared__ float As[2][16][GPAD];
    __shared__ float Bs[2][16][GPAD];

    const int tid  = threadIdx.x;
    const int lane = tid & 31;
    const int warp = tid >> 5;
    const int wm   = warp & 1;          // 0..1 (m slice of 64)
    const int wn   = warp >> 1;         // 0..3 (n slice of 32)
    const int qr   = lane >> 2;         // 0..7
    const int qc   = lane & 3;          // 0..3
    const int m0 = blockIdx.y * 128;
    const int n0 = blockIdx.x * 128;

    // global->shared mapping: each thread loads 8 contiguous K-floats of one row
    const int lr = tid >> 1;            // row in tile (0..127)
    const int lc = (tid & 1) << 3;      // k offset 0 or 8
    const float* Ap = X + (size_t)(m0 + lr) * K + lc;
    const float* Bp = W + (size_t)(n0 + lr) * K + lc;

    float acc[4][4][4];
#pragma unroll
    for (int i = 0; i < 4; i++)
#pragma unroll
        for (int j = 0; j < 4; j++)
#pragma unroll
            for (int r = 0; r < 4; r++) acc[i][j][r] = 0.0f;

    // preload tile 0 (transposed store, tf32-rounded)
    {
        float4 a0 = *(const float4*)(Ap + 0);
        float4 a1 = *(const float4*)(Ap + 4);
        float4 b0 = *(const float4*)(Bp + 0);
        float4 b1 = *(const float4*)(Bp + 4);
        As[0][lc + 0][lr] = to_tf32(a0.x); As[0][lc + 1][lr] = to_tf32(a0.y);
        As[0][lc + 2][lr] = to_tf32(a0.z); As[0][lc + 3][lr] = to_tf32(a0.w);
        As[0][lc + 4][lr] = to_tf32(a1.x); As[0][lc + 5][lr] = to_tf32(a1.y);
        As[0][lc + 6][lr] = to_tf32(a1.z); As[0][lc + 7][lr] = to_tf32(a1.w);
        Bs[0][lc + 0][lr] = to_tf32(b0.x); Bs[0][lc + 1][lr] = to_tf32(b0.y);
        Bs[0][lc + 2][lr] = to_tf32(b0.z); Bs[0][lc + 3][lr] = to_tf32(b0.w);
        Bs[0][lc + 4][lr] = to_tf32(b1.x); Bs[0][lc + 5][lr] = to_tf32(b1.y);
        Bs[0][lc + 6][lr] = to_tf32(b1.z); Bs[0][lc + 7][lr] = to_tf32(b1.w);
    }
    __syncthreads();

    const int T = K >> 4;
    int buf = 0;
    for (int t = 0; t < T; t++) {
        float4 a0n, a1n, b0n, b1n;
        const bool more = (t + 1 < T);
        if (more) {
            const int k0 = (t + 1) << 4;
            a0n = *(const float4*)(Ap + k0);
            a1n = *(const float4*)(Ap + k0 + 4);
            b0n = *(const float4*)(Bp + k0);
            b1n = *(const float4*)(Bp + k0 + 4);
        }

        // two k-steps of 8
#pragma unroll
        for (int ks = 0; ks < 16; ks += 8) {
            // A fragments: 4 m-tiles x 4 regs
            float af[4][4];
#pragma unroll
            for (int i = 0; i < 4; i++) {
                const int mb = wm * 64 + i * 16 + qr;
                af[i][0] = As[buf][ks + qc    ][mb];
                af[i][1] = As[buf][ks + qc    ][mb + 8];
                af[i][2] = As[buf][ks + qc + 4][mb];
                af[i][3] = As[buf][ks + qc + 4][mb + 8];
            }
            // B fragments: 4 n-tiles x 2 regs
            float bf[4][2];
#pragma unroll
            for (int j = 0; j < 4; j++) {
                const int nb = wn * 32 + j * 8 + qr;
                bf[j][0] = Bs[buf][ks + qc    ][nb];
                bf[j][1] = Bs[buf][ks + qc + 4][nb];
            }
#pragma unroll
            for (int i = 0; i < 4; i++)
#pragma unroll
                for (int j = 0; j < 4; j++) {
                    asm volatile(
                        "mma.sync.aligned.m16n8k8.row.col.f32.tf32.tf32.f32 "
                        "{%0,%1,%2,%3}, {%4,%5,%6,%7}, {%8,%9}, {%0,%1,%2,%3};"
                        : "+f"(acc[i][j][0]), "+f"(acc[i][j][1]),
                          "+f"(acc[i][j][2]), "+f"(acc[i][j][3])
                        : "r"(__float_as_uint(af[i][0])), "r"(__float_as_uint(af[i][1])),
                          "r"(__float_as_uint(af[i][2])), "r"(__float_as_uint(af[i][3])),
                          "r"(__float_as_uint(bf[j][0])), "r"(__float_as_uint(bf[j][1])));
                }
        }

        if (more) {
            const int nb = buf ^ 1;
            __syncthreads();   // everyone done reading buf before overwrite of nb? (nb untouched) -- needed to protect next-iter read of nb vs this store ordering across warps
            As[nb][lc + 0][lr] = to_tf32(a0n.x); As[nb][lc + 1][lr] = to_tf32(a0n.y);
            As[nb][lc + 2][lr] = to_tf32(a0n.z); As[nb][lc + 3][lr] = to_tf32(a0n.w);
            As[nb][lc + 4][lr] = to_tf32(a1n.x); As[nb][lc + 5][lr] = to_tf32(a1n.y);
            As[nb][lc + 6][lr] = to_tf32(a1n.z); As[nb][lc + 7][lr] = to_tf32(a1n.w);
            Bs[nb][lc + 0][lr] = to_tf32(b0n.x); Bs[nb][lc + 1][lr] = to_tf32(b0n.y);
            Bs[nb][lc + 2][lr] = to_tf32(b0n.z); Bs[nb][lc + 3][lr] = to_tf32(b0n.w);
            Bs[nb][lc + 4][lr] = to_tf32(b1n.x); Bs[nb][lc + 5][lr] = to_tf32(b1n.y);
            Bs[nb][lc + 6][lr] = to_tf32(b1n.z); Bs[nb][lc + 7][lr] = to_tf32(b1n.w);
            __syncthreads();
            buf = nb;
        }
    }

    // epilogue: c0,c1 at (row, col+0/1), c2,c3 at (row+8, col+0/1)
#pragma unroll
    for (int i = 0; i < 4; i++) {
        const int r0 = m0 + wm * 64 + i * 16 + qr;
#pragma unroll
        for (int j = 0; j < 4; j++) {
            const int c = n0 + wn * 32 + j * 8 + 2 * qc;
            float bv0 = 0.0f, bv1 = 0.0f;
            if (bias) { bv0 = bias[c]; bv1 = bias[c + 1]; }
            float v0 = acc[i][j][0] + bv0;
            float v1 = acc[i][j][1] + bv1;
            float v2 = acc[i][j][2] + bv0;
            float v3 = acc[i][j][3] + bv1;
            if (act) {
                v0 = gelu_exact(v0); v1 = gelu_exact(v1);
                v2 = gelu_exact(v2); v3 = gelu_exact(v3);
            }
            *(float2*)(Y + (size_t)r0 * N + c)       = make_float2(v0, v1);
            *(float2*)(Y + (size_t)(r0 + 8) * N + c) = make_float2(v2, v3);
        }
    }
}

// ---------------------------------------------------------------------------
// Flash attention (fp32, online softmax).
// grid: (N/64, B*H); block: 128 threads. BQ=64, BK=32, HD=64.
// ---------------------------------------------------------------------------
#define APAD 68
#define PPAD 36

__global__ void __launch_bounds__(128)
attn_kernel(const float* __restrict__ qkv, float* __restrict__ ctx)
{
    __shared__ float Qs[64][APAD];
    __shared__ float Ks[32][APAD];
    __shared__ float Vs[32][APAD];
    __shared__ float Ps[64][PPAD];

    const int bh = blockIdx.y;
    const int b = bh >> 4;
    const int h = bh & 15;
    const int q0 = blockIdx.x * 64;
    const int tid = threadIdx.x;
    const int row  = tid >> 1;
    const int half = tid & 1;
    const int doff = half * 32;
    const int joff = half * 16;

    for (int idx = tid; idx < 64 * 16; idx += 128) {
        const int i = idx >> 4;
        const int d4 = (idx & 15) << 2;
        const float* p = qkv + (size_t)(b * NN + q0 + i) * (3 * CC) + h * HD + d4;
        float4 v = *(const float4*)p;
        Qs[i][d4 + 0] = v.x * SCALE; Qs[i][d4 + 1] = v.y * SCALE;
        Qs[i][d4 + 2] = v.z * SCALE; Qs[i][d4 + 3] = v.w * SCALE;
    }

    float m = -INFINITY, l = 0.0f;
    float acc[32];
#pragma unroll
    for (int d = 0; d < 32; d++) acc[d] = 0.0f;

    for (int k0 = 0; k0 < NN; k0 += 32) {
        for (int idx = tid; idx < 32 * 16; idx += 128) {
            const int j = idx >> 4;
            const int d4 = (idx & 15) << 2;
            const size_t base = (size_t)(b * NN + k0 + j) * (3 * CC) + h * HD + d4;
            float4 kv = *(const float4*)(qkv + CC + base);
            float4 vv = *(const float4*)(qkv + 2 * CC + base);
            Ks[j][d4 + 0] = kv.x; Ks[j][d4 + 1] = kv.y;
            Ks[j][d4 + 2] = kv.z; Ks[j][d4 + 3] = kv.w;
            Vs[j][d4 + 0] = vv.x; Vs[j][d4 + 1] = vv.y;
            Vs[j][d4 + 2] = vv.z; Vs[j][d4 + 3] = vv.w;
        }
        __syncthreads();

        float s[16];
#pragma unroll
        for (int jj = 0; jj < 16; jj++) s[jj] = 0.0f;

#pragma unroll
        for (int d0 = 0; d0 < 64; d0 += 16) {
            float4 qa = *(const float4*)&Qs[row][d0 + 0];
            float4 qb = *(const float4*)&Qs[row][d0 + 4];
            float4 qc = *(const float4*)&Qs[row][d0 + 8];
            float4 qd = *(const float4*)&Qs[row][d0 + 12];
#pragma unroll 4
            for (int jj = 0; jj < 16; jj++) {
                const float* kr = &Ks[joff + jj][d0];
                float4 ka = *(const float4*)(kr + 0);
                float4 kb = *(const float4*)(kr + 4);
                float4 kc = *(const float4*)(kr + 8);
                float4 kd = *(const float4*)(kr + 12);
                float t = s[jj];
                t = fmaf(qa.x, ka.x, t); t = fmaf(qa.y, ka.y, t);
                t = fmaf(qa.z, ka.z, t); t = fmaf(qa.w, ka.w, t);
                t = fmaf(qb.x, kb.x, t); t = fmaf(qb.y, kb.y, t);
                t = fmaf(qb.z, kb.z, t); t = fmaf(qb.w, kb.w, t);
                t = fmaf(qc.x, kc.x, t); t = fmaf(qc.y, kc.y, t);
                t = fmaf(qc.z, kc.z, t); t = fmaf(qc.w, kc.w, t);
                t = fmaf(qd.x, kd.x, t); t = fmaf(qd.y, kd.y, t);
                t = fmaf(qd.z, kd.z, t); t = fmaf(qd.w, kd.w, t);
                s[jj] = t;
            }
        }

        float tmax = -INFINITY;
#pragma unroll
        for (int jj = 0; jj < 16; jj++) tmax = fmaxf(tmax, s[jj]);
        tmax = fmaxf(tmax, __shfl_xor_sync(0xffffffffu, tmax, 1));
        const float mnew = fmaxf(m, tmax);
        const float alpha = __expf(m - mnew);
        float lsum = 0.0f;
#pragma unroll
        for (int jj = 0; jj < 16; jj++) {
            float p = __expf(s[jj] - mnew);
            Ps[row][joff + jj] = p;
            lsum += p;
        }
        lsum += __shfl_xor_sync(0xffffffffu, lsum, 1);
        l = l * alpha + lsum;
        m = mnew;
#pragma unroll
        for (int d = 0; d < 32; d++) acc[d] *= alpha;
        __syncwarp();

#pragma unroll 4
        for (int j = 0; j < 32; j++) {
            const float p = Ps[row][j];
            const float* vr = &Vs[j][doff];
#pragma unroll
            for (int d4 = 0; d4 < 32; d4 += 4) {
                float4 v = *(const float4*)(vr + d4);
                acc[d4 + 0] = fmaf(p, v.x, acc[d4 + 0]);
                acc[d4 + 1] = fmaf(p, v.y, acc[d4 + 1]);
                acc[d4 + 2] = fmaf(p, v.z, acc[d4 + 2]);
                acc[d4 + 3] = fmaf(p, v.w, acc[d4 + 3]);
            }
        }
        __syncthreads();
    }

    const float inv = 1.0f / l;
    float* out = ctx + (size_t)(b * NN + q0 + row) * CC + h * HD + doff;
#pragma unroll
    for (int d4 = 0; d4 < 32; d4 += 4) {
        *(float4*)(out + d4) = make_float4(acc[d4] * inv, acc[d4 + 1] * inv,
                                           acc[d4 + 2] * inv, acc[d4 + 3] * inv);
    }
}

// ---------------------------------------------------------------------------
// dst[row] = base[row] + LayerNorm(x[row]) * w + b    (row length = 1024)
// ---------------------------------------------------------------------------
__global__ void __launch_bounds__(256)
residual_ln_kernel(const float* __restrict__ base, const float* __restrict__ x,
                   const float* __restrict__ w, const float* __restrict__ bvec,
                   float* __restrict__ dst)
{
    __shared__ float s_sum[8], s_sq[8];
    const int rowid = blockIdx.x;
    const int tid = threadIdx.x;
    const float4* xr = (const float4*)(x + (size_t)rowid * CC);

    float4 v = xr[tid];
    float sum = v.x + v.y + v.z + v.w;
    float sq  = v.x * v.x + v.y * v.y + v.z * v.z + v.w * v.w;

    const int lane = tid & 31, wid = tid >> 5;
#pragma unroll
    for (int o = 16; o; o >>= 1) {
        sum += __shfl_xor_sync(0xffffffffu, sum, o);
        sq  += __shfl_xor_sync(0xffffffffu, sq,  o);
    }
    if (lane == 0) { s_sum[wid] = sum; s_sq[wid] = sq; }
    __syncthreads();
    if (wid == 0) {
        sum = (lane < 8) ? s_sum[lane] : 0.0f;
        sq  = (lane < 8) ? s_sq[lane]  : 0.0f;
#pragma unroll
        for (int o = 4; o; o >>= 1) {
            sum += __shfl_xor_sync(0xffffffffu, sum, o);
            sq  += __shfl_xor_sync(0xffffffffu, sq,  o);
        }
        if (lane == 0) { s_sum[0] = sum; s_sq[0] = sq; }
    }
    __syncthreads();

    const float mu = s_sum[0] * (1.0f / CC);
    const float var = s_sq[0] * (1.0f / CC) - mu * mu;
    const float rstd = rsqrtf(var + 1e-5f);

    const float4* br = (const float4*)(base + (size_t)rowid * CC);
    const float4* wr = (const float4*)w;
    const float4* bb = (const float4*)bvec;
    float4 bs = br[tid], wv = wr[tid], bvv = bb[tid];
    float4 o;
    o.x = bs.x + (v.x - mu) * rstd * wv.x + bvv.x;
    o.y = bs.y + (v.y - mu) * rstd * wv.y + bvv.y;
    o.z = bs.z + (v.z - mu) * rstd * wv.z + bvv.z;
    o.w = bs.w + (v.w - mu) * rstd * wv.w + bvv.w;
    ((float4*)(dst + (size_t)rowid * CC))[tid] = o;
}

// ---------------------------------------------------------------------------
// Launch
// ---------------------------------------------------------------------------
extern "C" void kernel_launch(void* const* d_in, const int* in_sizes, int n_in,
                              void* d_out, int out_size)
{
    const float* x      = (const float*)d_in[0];
    const float* qkv_w  = (const float*)d_in[1];
    const float* proj_w = (const float*)d_in[2];
    const float* proj_b = (const float*)d_in[3];
    const float* ln1_w  = (const float*)d_in[4];
    const float* ln1_b  = (const float*)d_in[5];
    const float* fc1_w  = (const float*)d_in[6];
    const float* fc1_b  = (const float*)d_in[7];
    const float* fc2_w  = (const float*)d_in[8];
    const float* fc2_b  = (const float*)d_in[9];
    const float* ln2_w  = (const float*)d_in[10];
    const float* ln2_b  = (const float*)d_in[11];
    float* out = (float*)d_out;

    float *qkv, *ctx, *proj, *y1, *hbuf, *mlp;
    cudaGetSymbolAddress((void**)&qkv,  g_qkv);
    cudaGetSymbolAddress((void**)&ctx,  g_ctx);
    cudaGetSymbolAddress((void**)&proj, g_proj);
    cudaGetSymbolAddress((void**)&y1,   g_y1);
    cudaGetSymbolAddress((void**)&hbuf, g_h);
    cudaGetSymbolAddress((void**)&mlp,  g_mlp);

    // 1. qkv = x @ qkv_w^T                       [4096, 3072]
    gemm_tc_kernel<<<dim3(3 * CC / 128, MTOK / 128), 256>>>(
        x, qkv_w, nullptr, qkv, MTOK, 3 * CC, CC, 0);

    // 2. attention -> ctx                        [4096, 1024]
    attn_kernel<<<dim3(NN / 64, BB * HH), 128>>>(qkv, ctx);

    // 3. proj = ctx @ proj_w^T + proj_b          [4096, 1024]
    gemm_tc_kernel<<<dim3(CC / 128, MTOK / 128), 256>>>(
        ctx, proj_w, proj_b, proj, MTOK, CC, CC, 0);

    // 4. y1 = proj + LN(proj)
    residual_ln_kernel<<<MTOK, 256>>>(proj, proj, ln1_w, ln1_b, y1);

    // 5. h = gelu(y1 @ fc1_w^T + fc1_b)          [4096, 4096]
    gemm_tc_kernel<<<dim3(HID / 128, MTOK / 128), 256>>>(
        y1, fc1_w, fc1_b, hbuf, MTOK, HID, CC, 1);

    // 6. mlp = h @ fc2_w^T + fc2_b               [4096, 1024]
    gemm_tc_kernel<<<dim3(CC / 128, MTOK / 128), 256>>>(
        hbuf, fc2_w, fc2_b, mlp, MTOK, CC, HID, 0);

    // 7. out = y1 + LN(mlp)
    residual_ln_kernel<<<MTOK, 256>>>(y1, mlp, ln2_w, ln2_b, out);
}